// round 10
// baseline (speedup 1.0000x reference)
#include <cuda_runtime.h>
#include <math.h>
#include <stdint.h>

#define Bb 64
#define LL 512
#define DD 512

// ----------------------------- scratch ---------------------------------------
// A-fragment-layout tiles (8KB each): word ((mtile*2+kk)<<7)+phys*4+s
__device__ uint32_t g_tb[(size_t)Bb * 4 * 16 * 2048];     // masked t, bf16 (32MB)
__device__ uint32_t g_projb[(size_t)Bb * 4 * 16 * 2048];  // proj, bf16 (32MB)
// B-fragment-layout tiles (8KB each): word ((col>>3)*2+kk)*64+phys*2+s
__device__ uint32_t g_fb[(size_t)Bb * 4 * 16 * 2048];     // masked f, bf16 (32MB)
__device__ uint32_t g_wtb2[4 * 16 * 2048];                // W^T, bf16 (512KB)
__device__ float g_mt[Bb * LL];
__device__ float g_mf[Bb * LL];
__device__ float g_rowmax[Bb * LL];
__device__ float g_colmax[Bb * LL];
__device__ float g_alpha_t[Bb * LL];
__device__ float g_alpha_f[Bb * LL];
__device__ int   g_mask_fmt;

// ----------------------------- helpers ---------------------------------------
__device__ __forceinline__ uint32_t bf16x2_pack(float lo, float hi) {
    uint32_t r;
    asm("cvt.rn.bf16x2.f32 %0, %1, %2;" : "=r"(r) : "f"(hi), "f"(lo));
    return r;
}

__device__ __forceinline__ void mma_bf16(float* c, const uint32_t* a, const uint32_t* b) {
    asm volatile(
        "mma.sync.aligned.m16n8k16.row.col.f32.bf16.bf16.f32 "
        "{%0,%1,%2,%3}, {%4,%5,%6,%7}, {%8,%9}, {%0,%1,%2,%3};\n"
        : "+f"(c[0]), "+f"(c[1]), "+f"(c[2]), "+f"(c[3])
        : "r"(a[0]), "r"(a[1]), "r"(a[2]), "r"(a[3]), "r"(b[0]), "r"(b[1]));
}

#define CP_ASYNC16(sm_u32, gptr) \
    asm volatile("cp.async.cg.shared.global [%0], [%1], 16;" \
                 :: "r"(sm_u32), "l"(gptr) : "memory")
#define CP_COMMIT() asm volatile("cp.async.commit_group;" ::: "memory")
#define CP_WAIT1()  asm volatile("cp.async.wait_group 1;" ::: "memory")
#define CP_WAIT0()  asm volatile("cp.async.wait_group 0;" ::: "memory")

__device__ __forceinline__ void atomicMaxF(float* a, float v) {
    if (v >= 0.0f) atomicMax((int*)a, __float_as_int(v));
    else           atomicMin((unsigned int*)a, __float_as_uint(v));
}

__device__ __forceinline__ float load_mask(const void* p, int i, int fmt) {
    if (fmt == 0) return ((const int*)p)[i] ? 1.0f : 0.0f;
    if (fmt == 1) return ((const float*)p)[i];
    return ((const unsigned char*)p)[i] ? 1.0f : 0.0f;
}

// ---- bf16 fragment-layout writers (mapping validated R5-R9) --------------------
__device__ __forceinline__ void stA_bf(uint32_t* dst, int row, int kk, int p0,
                                       float4 v, float m) {
    uint32_t w0 = bf16x2_pack(v.x * m, v.y * m);
    uint32_t w1 = bf16x2_pack(v.z * m, v.w * m);
    const int base = (((row >> 4) * 2 + kk) << 7) + ((row & 15) >> 3);
    const int rl = (row & 7) * 4;
    int lane = rl + (p0 & 3), phys = lane ^ (lane >> 3);
    dst[base + phys * 4 + ((p0 >> 2) << 1)] = w0;
    int p = p0 + 1;
    lane = rl + (p & 3); phys = lane ^ (lane >> 3);
    dst[base + phys * 4 + ((p >> 2) << 1)] = w1;
}

__device__ __forceinline__ void stB_bf(uint32_t* dst, int col, int kk, int p0,
                                       float4 v, float m) {
    uint32_t w0 = bf16x2_pack(v.x * m, v.y * m);
    uint32_t w1 = bf16x2_pack(v.z * m, v.w * m);
    const int base = (((col >> 3) * 2 + kk) << 6);
    const int rl = (col & 7) * 4;
    int lane = rl + (p0 & 3), phys = lane ^ (lane >> 3);
    dst[base + phys * 2 + (p0 >> 2)] = w0;
    int p = p0 + 1;
    lane = rl + (p & 3); phys = lane ^ (lane >> 3);
    dst[base + phys * 2 + (p >> 2)] = w1;
}

// ---- shared MMA block -----------------------------------------------------------
__device__ __forceinline__ void mma_block(const uint32_t* Asb, const uint32_t* Bsb,
                                          int kk, int wm, int wn, int physL,
                                          float acc[4][4][4]) {
    uint4 af[4]; uint2 bfv[4];
#pragma unroll
    for (int mt = 0; mt < 4; mt++)
        af[mt] = *(const uint4*)&Asb[(((wm * 4 + mt) * 2 + kk) << 7) + physL * 4];
#pragma unroll
    for (int nt = 0; nt < 4; nt++)
        bfv[nt] = *(const uint2*)&Bsb[(((wn * 4 + nt) * 2 + kk) << 6) + physL * 2];
#pragma unroll
    for (int mt = 0; mt < 4; mt++)
#pragma unroll
        for (int nt = 0; nt < 4; nt++)
            mma_bf16(acc[mt][nt], (const uint32_t*)&af[mt], (const uint32_t*)&bfv[nt]);
}

// ----------------------------- small kernels ----------------------------------
__global__ void detect_kernel(const unsigned int* m) {
    int lane = threadIdx.x;
    bool i32 = true, f32 = true;
    for (int i = lane; i < 256; i += 32) {
        unsigned int w = m[i];
        i32 = i32 && (w <= 1u);
        f32 = f32 && (w == 0u || w == 0x3F800000u);
    }
    i32 = __all_sync(0xffffffffu, i32);
    f32 = __all_sync(0xffffffffu, f32);
    if (lane == 0) g_mask_fmt = i32 ? 0 : (f32 ? 1 : 2);
}

__global__ void prep_kernel(const void* mt, const void* mf) {
    int i = blockIdx.x * blockDim.x + threadIdx.x;
    if (i >= Bb * LL) return;
    int fmt = g_mask_fmt;
    g_mt[i] = load_mask(mt, i, fmt);
    g_mf[i] = load_mask(mf, i, fmt);
    float ninf = __int_as_float(0xff800000);
    g_rowmax[i] = ninf;
    g_colmax[i] = ninf;
}

// pack W into B-fragment-layout tiles: blockIdx.x = k-pair p (0..255), tid = n
__global__ void pack_w(const float* __restrict__ W) {
    const int p = blockIdx.x;
    const int n = threadIdx.x;          // 512 threads
    const int k0 = p * 2;
    float lo = W[(size_t)k0 * DD + n];
    float hi = W[(size_t)(k0 + 1) * DD + n];
    const int nt = n >> 7, col = n & 127;
    const int kt = p >> 4, kk = (p >> 3) & 1, pl = p & 7;
    const int lane_v = (col & 7) * 4 + (pl & 3);
    const int phys = lane_v ^ (lane_v >> 3);
    const int idx = (nt * 16 + kt) * 2048 +
                    (((col >> 3) * 2 + kk) << 6) + phys * 2 + (pl >> 2);
    g_wtb2[idx] = bf16x2_pack(lo, hi);
}

// pack t (masked) into A-fragment tiles: grid (16 kt, 4 lt, Bb), block 256
__global__ void pack_t_kernel(const float* __restrict__ T) {
    const int kt = blockIdx.x, lt = blockIdx.y, b = blockIdx.z;
    const int tid = threadIdx.x;
    const int row = tid >> 1, h = tid & 1;     // h = kk (16-k half)
    const float m = g_mt[b * LL + lt * 128 + row];
    const float* src = T + ((size_t)b * LL + lt * 128 + row) * DD + kt * 32 + h * 16;
    uint32_t* dst = g_tb + ((((size_t)b * 4 + lt) * 16) + kt) * 2048;
    float4 v0 = *(const float4*)(src);
    float4 v1 = *(const float4*)(src + 4);
    float4 v2 = *(const float4*)(src + 8);
    float4 v3 = *(const float4*)(src + 12);
    stA_bf(dst, row, h, 0, v0, m);
    stA_bf(dst, row, h, 2, v1, m);
    stA_bf(dst, row, h, 4, v2, m);
    stA_bf(dst, row, h, 6, v3, m);
}

// pack f (masked) into B-fragment tiles: grid (16 kt, 4 nt, Bb), block 256
__global__ void pack_f_kernel(const float* __restrict__ F) {
    const int kt = blockIdx.x, nt = blockIdx.y, b = blockIdx.z;
    const int tid = threadIdx.x;
    const int col = tid >> 1, h = tid & 1;
    const float m = g_mf[b * LL + nt * 128 + col];
    const float* src = F + ((size_t)b * LL + nt * 128 + col) * DD + kt * 32 + h * 16;
    uint32_t* dst = g_fb + ((((size_t)b * 4 + nt) * 16) + kt) * 2048;
    float4 v0 = *(const float4*)(src);
    float4 v1 = *(const float4*)(src + 4);
    float4 v2 = *(const float4*)(src + 8);
    float4 v3 = *(const float4*)(src + 12);
    stB_bf(dst, col, h, 0, v0, m);
    stB_bf(dst, col, h, 2, v1, m);
    stB_bf(dst, col, h, 4, v2, m);
    stB_bf(dst, col, h, 6, v3, m);
}

// ----------------------------- dual-cp.async GEMM --------------------------------
// MODE 0: D = tb @ wtb^T  -> proj tiles (A-frag layout)
// MODE 1: M = projb @ fb^T -> fused row/col max
template <int MODE>
__global__ void __launch_bounds__(256, 3) gemm_kernel()
{
    extern __shared__ uint32_t sh[];   // [0,6144): A stages x3, [6144,12288): B stages x3
    __shared__ float s_rmax[128];
    __shared__ float s_cmax[128];

    const int tid  = threadIdx.x;
    const int lane = tid & 31;
    const int wid  = tid >> 5;
    const int wm   = wid & 1;
    const int wn   = wid >> 1;
    const int b  = blockIdx.z;
    const int nt_tile = blockIdx.x;
    const int lt = blockIdx.y;
    const int physL = lane ^ (lane >> 3);
    const float NINF = __int_as_float(0xff800000);

    const uint32_t* At = (MODE == 0 ? g_tb : g_projb)
                       + (((size_t)b * 4 + lt) * 16) * 2048 + tid * 8;
    const uint32_t* Bt = (MODE == 0 ? g_wtb2 + (size_t)nt_tile * 16 * 2048
                                    : g_fb + (((size_t)b * 4 + nt_tile) * 16) * 2048)
                       + tid * 8;

    if (MODE == 1 && tid < 128) { s_rmax[tid] = NINF; s_cmax[tid] = NINF; }

    const uint32_t shA = (uint32_t)__cvta_generic_to_shared(sh) + tid * 32;
    const uint32_t shB = shA + 6144 * 4;

    float acc[4][4][4];
#pragma unroll
    for (int i = 0; i < 4; i++)
#pragma unroll
        for (int j = 0; j < 4; j++)
#pragma unroll
            for (int q = 0; q < 4; q++) acc[i][j][q] = 0.0f;

    // prologue: stages 0,1 in flight
    CP_ASYNC16(shA,      At);      CP_ASYNC16(shA + 16, At + 4);
    CP_ASYNC16(shB,      Bt);      CP_ASYNC16(shB + 16, Bt + 4);
    CP_COMMIT();
    CP_ASYNC16(shA + 8192,      At + 2048); CP_ASYNC16(shA + 8192 + 16, At + 2048 + 4);
    CP_ASYNC16(shB + 8192,      Bt + 2048); CP_ASYNC16(shB + 8192 + 16, Bt + 2048 + 4);
    CP_COMMIT();
    CP_WAIT1();
    __syncthreads();

    for (int kt = 0; kt < 16; kt++) {
        const int s = kt % 3;
        if (kt + 2 < 16) {
            const int s2 = (kt + 2) % 3;
            CP_ASYNC16(shA + s2 * 8192,      At + (size_t)(kt + 2) * 2048);
            CP_ASYNC16(shA + s2 * 8192 + 16, At + (size_t)(kt + 2) * 2048 + 4);
            CP_ASYNC16(shB + s2 * 8192,      Bt + (size_t)(kt + 2) * 2048);
            CP_ASYNC16(shB + s2 * 8192 + 16, Bt + (size_t)(kt + 2) * 2048 + 4);
            CP_COMMIT();
        }
        const uint32_t* Asb = sh + s * 2048;
        const uint32_t* Bsb = sh + 6144 + s * 2048;
        mma_block(Asb, Bsb, 0, wm, wn, physL, acc);
        mma_block(Asb, Bsb, 1, wm, wn, physL, acc);
        if (kt + 1 < 16) {
            if (kt + 2 < 16) { CP_WAIT1(); } else { CP_WAIT0(); }
            __syncthreads();
        }
    }

    const int lx = lane & 3, ly = lane >> 2;
    if (MODE == 0) {
        // write proj tiles in EXACT mma_block A-fragment layout (validated R9)
        uint32_t* Ptile = g_projb + (((size_t)b * 4 + lt) * 16) * 2048;
#pragma unroll
        for (int mt = 0; mt < 4; mt++) {
            const int mtile = wm * 4 + mt;
#pragma unroll
            for (int nt = 0; nt < 4; nt++) {
                const int c = nt_tile * 128 + wn * 32 + nt * 8 + 2 * lx;
                const int kp_g = c >> 1;
                const int kt1 = kp_g >> 4;
                const int kk1 = (kp_g >> 3) & 1;
                const int kp  = kp_g & 7;
                const int lane_v = ly * 4 + (kp & 3);
                const int phys = lane_v ^ (lane_v >> 3);
                const int si = (kp >= 4) ? 2 : 0;
                const int idx = kt1 * 2048 + (((mtile * 2 + kk1) << 7)) + phys * 4 + si;
                uint2 w;
                w.x = bf16x2_pack(acc[mt][nt][0], acc[mt][nt][1]);
                w.y = bf16x2_pack(acc[mt][nt][2], acc[mt][nt][3]);
                *(uint2*)&Ptile[idx] = w;
            }
        }
    } else {
        __syncthreads();
#pragma unroll
        for (int mt = 0; mt < 4; mt++) {
#pragma unroll
            for (int h = 0; h < 2; h++) {
                float v = NINF;
#pragma unroll
                for (int nt = 0; nt < 4; nt++)
                    v = fmaxf(v, fmaxf(acc[mt][nt][2 * h], acc[mt][nt][2 * h + 1]));
                v = fmaxf(v, __shfl_xor_sync(0xffffffffu, v, 1));
                v = fmaxf(v, __shfl_xor_sync(0xffffffffu, v, 2));
                if (lx == 0) atomicMaxF(&s_rmax[wm * 64 + mt * 16 + ly + h * 8], v);
            }
        }
#pragma unroll
        for (int nt = 0; nt < 4; nt++) {
#pragma unroll
            for (int j = 0; j < 2; j++) {
                float v = NINF;
#pragma unroll
                for (int mt = 0; mt < 4; mt++)
                    v = fmaxf(v, fmaxf(acc[mt][nt][j], acc[mt][nt][2 + j]));
                v = fmaxf(v, __shfl_xor_sync(0xffffffffu, v, 4));
                v = fmaxf(v, __shfl_xor_sync(0xffffffffu, v, 8));
                v = fmaxf(v, __shfl_xor_sync(0xffffffffu, v, 16));
                if (lane < 4) atomicMaxF(&s_cmax[wn * 32 + nt * 8 + 2 * lane + j], v);
            }
        }
        __syncthreads();
        if (tid < 128) {
            atomicMaxF(&g_rowmax[b * LL + lt * 128 + tid], s_rmax[tid]);
            atomicMaxF(&g_colmax[b * LL + nt_tile * 128 + tid], s_cmax[tid]);
        }
    }
}

// ----------------------------- softmax ----------------------------------------
__global__ void softmax_kernel() {
    const int idx = blockIdx.x;
    const bool isF = idx >= Bb;
    const int b = isF ? idx - Bb : idx;
    const float* mx = isF ? (g_colmax + b * LL) : (g_rowmax + b * LL);
    const float* mk = isF ? (g_mf + b * LL) : (g_mt + b * LL);
    float* out = isF ? (g_alpha_f + b * LL) : (g_alpha_t + b * LL);

    const int tid = threadIdx.x;
    int i0 = tid, i1 = tid + 256;
    float m0v = mk[i0], m1v = mk[i1];
    float v0 = tanhf(mx[i0]) + (m0v - 1.0f) * 1000000.0f;
    float v1 = tanhf(mx[i1]) + (m1v - 1.0f) * 1000000.0f;

    __shared__ float red[256];
    red[tid] = fmaxf(v0, v1);
    __syncthreads();
    for (int s = 128; s > 0; s >>= 1) {
        if (tid < s) red[tid] = fmaxf(red[tid], red[tid + s]);
        __syncthreads();
    }
    float vm = red[0];
    __syncthreads();

    float e0 = expf(v0 - vm);
    float e1 = expf(v1 - vm);
    red[tid] = e0 + e1;
    __syncthreads();
    for (int s = 128; s > 0; s >>= 1) {
        if (tid < s) red[tid] += red[tid + s];
        __syncthreads();
    }
    float inv = 1.0f / red[0];
    out[i0] = e0 * inv * m0v;
    out[i1] = e1 * inv * m1v;
}

// ----------------------------- combine -----------------------------------------
// grid (4, Bb), block 1024: 8 L-chunks of 64 per (b, d-group), smem reduce.
__global__ void combine_kernel(const float* __restrict__ T,
                               const float* __restrict__ F,
                               float* __restrict__ out)
{
    __shared__ float red[1024];
    const int b = blockIdx.y;
    const int dl = threadIdx.x & 127;
    const int chunk = threadIdx.x >> 7;           // 0..7
    const int d = blockIdx.x * 128 + dl;
    const float* at = g_alpha_t + b * LL;
    const float* af = g_alpha_f + b * LL;
    const float* tp = T + (size_t)b * LL * DD + d;
    const float* fp = F + (size_t)b * LL * DD + d;
    const int lb = chunk * 64;

    float a0 = 0.f, a1 = 0.f, a2 = 0.f, a3 = 0.f;
    float c0 = 0.f, c1 = 0.f, c2 = 0.f, c3 = 0.f;
#pragma unroll 2
    for (int l = lb; l < lb + 64; l += 8) {
        a0 = fmaf(at[l + 0], tp[(size_t)(l + 0) * DD], a0);
        a1 = fmaf(at[l + 1], tp[(size_t)(l + 1) * DD], a1);
        a2 = fmaf(at[l + 2], tp[(size_t)(l + 2) * DD], a2);
        a3 = fmaf(at[l + 3], tp[(size_t)(l + 3) * DD], a3);
        c0 = fmaf(at[l + 4], tp[(size_t)(l + 4) * DD], c0);
        c1 = fmaf(at[l + 5], tp[(size_t)(l + 5) * DD], c1);
        c2 = fmaf(at[l + 6], tp[(size_t)(l + 6) * DD], c2);
        c3 = fmaf(at[l + 7], tp[(size_t)(l + 7) * DD], c3);
    }
#pragma unroll 2
    for (int m = lb; m < lb + 64; m += 8) {
        a0 = fmaf(af[m + 0], fp[(size_t)(m + 0) * DD], a0);
        a1 = fmaf(af[m + 1], fp[(size_t)(m + 1) * DD], a1);
        a2 = fmaf(af[m + 2], fp[(size_t)(m + 2) * DD], a2);
        a3 = fmaf(af[m + 3], fp[(size_t)(m + 3) * DD], a3);
        c0 = fmaf(af[m + 4], fp[(size_t)(m + 4) * DD], c0);
        c1 = fmaf(af[m + 5], fp[(size_t)(m + 5) * DD], c1);
        c2 = fmaf(af[m + 6], fp[(size_t)(m + 6) * DD], c2);
        c3 = fmaf(af[m + 7], fp[(size_t)(m + 7) * DD], c3);
    }
    red[threadIdx.x] = ((a0 + a1) + (a2 + a3)) + ((c0 + c1) + (c2 + c3));
    __syncthreads();
    if (chunk == 0) {
        float s = 0.f;
#pragma unroll
        for (int i = 0; i < 8; i++) s += red[dl + 128 * i];
        out[b * DD + d] = s;
    }
}

// ----------------------------- launch -------------------------------------------
extern "C" void kernel_launch(void* const* d_in, const int* in_sizes, int n_in,
                              void* d_out, int out_size)
{
    const float* t  = (const float*)d_in[0];
    const float* f  = (const float*)d_in[1];
    const void*  mt = d_in[2];
    const void*  mf = d_in[3];
    const float* w  = (const float*)d_in[4];
    float* out = (float*)d_out;

    const int GSMEM = 12288 * 4;   // 48 KB dynamic
    cudaFuncSetAttribute(gemm_kernel<0>, cudaFuncAttributeMaxDynamicSharedMemorySize, GSMEM);
    cudaFuncSetAttribute(gemm_kernel<1>, cudaFuncAttributeMaxDynamicSharedMemorySize, GSMEM);

    detect_kernel<<<1, 32>>>((const unsigned int*)mt);
    prep_kernel<<<(Bb * LL + 255) / 256, 256>>>(mt, mf);
    pack_w<<<256, 512>>>(w);
    pack_t_kernel<<<dim3(16, 4, Bb), 256>>>(t);
    pack_f_kernel<<<dim3(16, 4, Bb), 256>>>(f);
    gemm_kernel<0><<<dim3(4, 4, Bb), 256, GSMEM>>>();
    gemm_kernel<1><<<dim3(4, 4, Bb), 256, GSMEM>>>();
    softmax_kernel<<<2 * Bb, 256>>>();
    combine_kernel<<<dim3(4, Bb), 1024>>>(t, f, out);
}

// round 11
// speedup vs baseline: 1.6140x; 1.6140x over previous
#include <cuda_runtime.h>
#include <math.h>
#include <stdint.h>

#define Bb 64
#define LL 512
#define DD 512

// ----------------------------- scratch ---------------------------------------
// proj tiles (8KB) in EXACT mma_block A-fragment order, compact-M rows
__device__ uint32_t g_projb[(size_t)Bb * 4 * 16 * 2048];
// W^T tiles (8KB) in EXACT mma_block B-fragment order
__device__ uint32_t g_wtb2[4 * 16 * 2048];
__device__ float g_mt[Bb * LL];
__device__ float g_mf[Bb * LL];
__device__ int   g_idx_t[Bb * LL];
__device__ int   g_idx_f[Bb * LL];
__device__ int   g_cnt_t[Bb];
__device__ int   g_cnt_f[Bb];
__device__ float g_rowmax[Bb * LL];
__device__ float g_colmax[Bb * LL];
__device__ float g_alpha_t[Bb * LL];
__device__ float g_alpha_f[Bb * LL];
__device__ int   g_mask_fmt;

// ----------------------------- helpers ---------------------------------------
__device__ __forceinline__ uint32_t bf16x2_pack(float lo, float hi) {
    uint32_t r;
    asm("cvt.rn.bf16x2.f32 %0, %1, %2;" : "=r"(r) : "f"(hi), "f"(lo));
    return r;
}

__device__ __forceinline__ void mma_bf16(float* c, const uint32_t* a, const uint32_t* b) {
    asm volatile(
        "mma.sync.aligned.m16n8k16.row.col.f32.bf16.bf16.f32 "
        "{%0,%1,%2,%3}, {%4,%5,%6,%7}, {%8,%9}, {%0,%1,%2,%3};\n"
        : "+f"(c[0]), "+f"(c[1]), "+f"(c[2]), "+f"(c[3])
        : "r"(a[0]), "r"(a[1]), "r"(a[2]), "r"(a[3]), "r"(b[0]), "r"(b[1]));
}

#define CP_ASYNC16(sm_u32, gptr) \
    asm volatile("cp.async.cg.shared.global [%0], [%1], 16;" \
                 :: "r"(sm_u32), "l"(gptr) : "memory")
#define CP_COMMIT() asm volatile("cp.async.commit_group;" ::: "memory")
#define CP_WAIT1()  asm volatile("cp.async.wait_group 1;" ::: "memory")
#define CP_WAIT0()  asm volatile("cp.async.wait_group 0;" ::: "memory")

__device__ __forceinline__ void atomicMaxF(float* a, float v) {
    if (v >= 0.0f) atomicMax((int*)a, __float_as_int(v));
    else           atomicMin((unsigned int*)a, __float_as_uint(v));
}

__device__ __forceinline__ float load_mask(const void* p, int i, int fmt) {
    if (fmt == 0) return ((const int*)p)[i] ? 1.0f : 0.0f;
    if (fmt == 1) return ((const float*)p)[i];
    return ((const unsigned char*)p)[i] ? 1.0f : 0.0f;
}

// ---- bf16 fragment-layout writers (mapping validated R5-R9), no-mask variants ---
__device__ __forceinline__ void stA_nm(uint32_t* dst, int row, int kk, int p0, float4 v) {
    uint32_t w0 = bf16x2_pack(v.x, v.y);
    uint32_t w1 = bf16x2_pack(v.z, v.w);
    const int base = (((row >> 4) * 2 + kk) << 7) + ((row & 15) >> 3);
    const int rl = (row & 7) * 4;
    int lane = rl + (p0 & 3), phys = lane ^ (lane >> 3);
    dst[base + phys * 4 + ((p0 >> 2) << 1)] = w0;
    int p = p0 + 1;
    lane = rl + (p & 3); phys = lane ^ (lane >> 3);
    dst[base + phys * 4 + ((p >> 2) << 1)] = w1;
}

__device__ __forceinline__ void stB_nm(uint32_t* dst, int col, int kk, int p0, float4 v) {
    uint32_t w0 = bf16x2_pack(v.x, v.y);
    uint32_t w1 = bf16x2_pack(v.z, v.w);
    const int base = (((col >> 3) * 2 + kk) << 6);
    const int rl = (col & 7) * 4;
    int lane = rl + (p0 & 3), phys = lane ^ (lane >> 3);
    dst[base + phys * 2 + (p0 >> 2)] = w0;
    int p = p0 + 1;
    lane = rl + (p & 3); phys = lane ^ (lane >> 3);
    dst[base + phys * 2 + (p >> 2)] = w1;
}

__device__ __forceinline__ float4 zmask(float4 v, bool pred) {
    if (!pred) { v.x = 0.f; v.y = 0.f; v.z = 0.f; v.w = 0.f; }
    return v;
}

// ---- shared MMA block -----------------------------------------------------------
__device__ __forceinline__ void mma_block(const uint32_t* Asb, const uint32_t* Bsb,
                                          int kk, int wm, int wn, int physL,
                                          float acc[4][4][4]) {
    uint4 af[4]; uint2 bfv[4];
#pragma unroll
    for (int mt = 0; mt < 4; mt++)
        af[mt] = *(const uint4*)&Asb[(((wm * 4 + mt) * 2 + kk) << 7) + physL * 4];
#pragma unroll
    for (int nt = 0; nt < 4; nt++)
        bfv[nt] = *(const uint2*)&Bsb[(((wn * 4 + nt) * 2 + kk) << 6) + physL * 2];
#pragma unroll
    for (int mt = 0; mt < 4; mt++)
#pragma unroll
        for (int nt = 0; nt < 4; nt++)
            mma_bf16(acc[mt][nt], (const uint32_t*)&af[mt], (const uint32_t*)&bfv[nt]);
}

// ----------------------------- small kernels ----------------------------------
__global__ void detect_kernel(const unsigned int* m) {
    int lane = threadIdx.x;
    bool i32 = true, f32 = true;
    for (int i = lane; i < 256; i += 32) {
        unsigned int w = m[i];
        i32 = i32 && (w <= 1u);
        f32 = f32 && (w == 0u || w == 0x3F800000u);
    }
    i32 = __all_sync(0xffffffffu, i32);
    f32 = __all_sync(0xffffffffu, f32);
    if (lane == 0) g_mask_fmt = i32 ? 0 : (f32 ? 1 : 2);
}

// per (b, which) block of 512: mask expand + compaction prefix-sum + max init
__global__ void compact_kernel(const void* mt, const void* mf) {
    const int x = blockIdx.x;
    const int b = x >> 1;
    const bool isF = x & 1;
    const int tid = threadIdx.x;
    const int fmt = g_mask_fmt;
    const float mv = load_mask(isF ? mf : mt, b * LL + tid, fmt);
    (isF ? g_mf : g_mt)[b * LL + tid] = mv;
    (isF ? g_colmax : g_rowmax)[b * LL + tid] = __int_as_float(0xff800000);

    const bool on = (mv != 0.0f);
    const unsigned bal = __ballot_sync(0xffffffffu, on);
    __shared__ int wsum[16];
    __shared__ int wbase[16];
    const int wid = tid >> 5, lane = tid & 31;
    if (lane == 0) wsum[wid] = __popc(bal);
    __syncthreads();
    if (tid == 0) {
        int s = 0;
        for (int i = 0; i < 16; i++) { wbase[i] = s; s += wsum[i]; }
        if (isF) g_cnt_f[b] = s; else g_cnt_t[b] = s;
    }
    __syncthreads();
    if (on) {
        int pos = wbase[wid] + __popc(bal & ((1u << lane) - 1u));
        (isF ? g_idx_f : g_idx_t)[b * LL + pos] = tid;
    }
}

// pack W into B-fragment-layout tiles: blockIdx.x = k-pair p (0..255), tid = n
__global__ void pack_w(const float* __restrict__ W) {
    const int p = blockIdx.x;
    const int n = threadIdx.x;          // 512 threads
    const int k0 = p * 2;
    float lo = W[(size_t)k0 * DD + n];
    float hi = W[(size_t)(k0 + 1) * DD + n];
    const int nt = n >> 7, col = n & 127;
    const int kt = p >> 4, kk = (p >> 3) & 1, pl = p & 7;
    const int lane_v = (col & 7) * 4 + (pl & 3);
    const int phys = lane_v ^ (lane_v >> 3);
    const int idx = (nt * 16 + kt) * 2048 +
                    (((col >> 3) * 2 + kk) << 6) + phys * 2 + (pl >> 2);
    g_wtb2[idx] = bf16x2_pack(lo, hi);
}

// ----------------------------- GEMM 0: proj = compact(t) @ W^T ------------------
// A (compact t rows) via registers (2-stage); B (W) via cp.async (3-stage).
__global__ void __launch_bounds__(256, 2) gemm0_kernel(const float* __restrict__ T)
{
    __shared__ __align__(16) uint32_t As[2][2048];
    __shared__ __align__(16) uint32_t Bs[3][2048];

    const int tid  = threadIdx.x;
    const int lane = tid & 31;
    const int wid  = tid >> 5;
    const int wm   = wid & 1;
    const int wn   = wid >> 1;
    const int b  = blockIdx.z;
    const int l0 = blockIdx.y * 128;
    const int nt_tile = blockIdx.x;

    const int cnt = g_cnt_t[b];
    if (l0 >= cnt) return;

    const int gr = tid >> 2;
    const int gc = (tid & 3) * 4;
    const int p0 = gc >> 1;
    const int physL = lane ^ (lane >> 3);

    const int j0 = l0 + gr, j1 = l0 + gr + 64;
    const bool pr0 = (j0 < cnt), pr1 = (j1 < cnt);
    const int r0 = pr0 ? g_idx_t[b * LL + j0] : 0;
    const int r1 = pr1 ? g_idx_t[b * LL + j1] : 0;

    const float* Ab0 = T + ((size_t)b * LL + r0) * DD + gc;
    const float* Ab1 = T + ((size_t)b * LL + r1) * DD + gc;
    const uint32_t* Wtile = g_wtb2 + (size_t)nt_tile * 16 * 2048 + tid * 8;

    uint32_t bs_u32[3];
#pragma unroll
    for (int s = 0; s < 3; s++)
        bs_u32[s] = (uint32_t)__cvta_generic_to_shared(&Bs[s][tid * 8]);

    float acc[4][4][4];
#pragma unroll
    for (int i = 0; i < 4; i++)
#pragma unroll
        for (int j = 0; j < 4; j++)
#pragma unroll
            for (int q = 0; q < 4; q++) acc[i][j][q] = 0.0f;

    // prologue
    CP_ASYNC16(bs_u32[0],      Wtile);
    CP_ASYNC16(bs_u32[0] + 16, Wtile + 4);
    CP_COMMIT();
    CP_ASYNC16(bs_u32[1],      Wtile + 2048);
    CP_ASYNC16(bs_u32[1] + 16, Wtile + 2048 + 4);
    CP_COMMIT();
    {
        float4 v;
        v = zmask(*(const float4*)(Ab0), pr0);      stA_nm(As[0], gr,      0, p0, v);
        v = zmask(*(const float4*)(Ab0 + 16), pr0); stA_nm(As[0], gr,      1, p0, v);
        v = zmask(*(const float4*)(Ab1), pr1);      stA_nm(As[0], gr + 64, 0, p0, v);
        v = zmask(*(const float4*)(Ab1 + 16), pr1); stA_nm(As[0], gr + 64, 1, p0, v);
    }
    CP_WAIT1();
    __syncthreads();

    for (int kt = 0; kt < 16; kt++) {
        const int buf2 = kt & 1;
        const int buf3 = kt % 3;
        const bool more = (kt + 1 < 16);

        float4 va0, va1, va2, va3;
        if (more) {
            const int K0 = (kt + 1) * 32;
            va0 = zmask(*(const float4*)(Ab0 + K0), pr0);
            va1 = zmask(*(const float4*)(Ab0 + K0 + 16), pr0);
            va2 = zmask(*(const float4*)(Ab1 + K0), pr1);
            va3 = zmask(*(const float4*)(Ab1 + K0 + 16), pr1);
        }
        if (kt + 2 < 16) {
            const int s3 = (kt + 2) % 3;
            CP_ASYNC16(bs_u32[s3],      Wtile + (size_t)(kt + 2) * 2048);
            CP_ASYNC16(bs_u32[s3] + 16, Wtile + (size_t)(kt + 2) * 2048 + 4);
            CP_COMMIT();
        }

        mma_block(As[buf2], Bs[buf3], 0, wm, wn, physL, acc);

        if (more) {
            stA_nm(As[buf2 ^ 1], gr,      0, p0, va0);
            stA_nm(As[buf2 ^ 1], gr,      1, p0, va1);
            stA_nm(As[buf2 ^ 1], gr + 64, 0, p0, va2);
            stA_nm(As[buf2 ^ 1], gr + 64, 1, p0, va3);
        }

        mma_block(As[buf2], Bs[buf3], 1, wm, wn, physL, acc);

        if (more) {
            if (kt + 2 < 16) { CP_WAIT1(); } else { CP_WAIT0(); }
            __syncthreads();
        }
    }

    // epilogue: proj tiles in EXACT mma_block A-fragment layout (validated R9)
    const int lx = lane & 3, ly = lane >> 2;
    uint32_t* Ptile = g_projb + ((size_t)b * 4 + blockIdx.y) * 16 * 2048;
#pragma unroll
    for (int mt = 0; mt < 4; mt++) {
        const int mtile = wm * 4 + mt;
#pragma unroll
        for (int nt = 0; nt < 4; nt++) {
            const int c = nt_tile * 128 + wn * 32 + nt * 8 + 2 * lx;
            const int kp_g = c >> 1;
            const int kt1 = kp_g >> 4;
            const int kk1 = (kp_g >> 3) & 1;
            const int kp  = kp_g & 7;
            const int lane_v = ly * 4 + (kp & 3);
            const int phys = lane_v ^ (lane_v >> 3);
            const int si = (kp >= 4) ? 2 : 0;
            const int idx = kt1 * 2048 + (((mtile * 2 + kk1) << 7)) + phys * 4 + si;
            uint2 w;
            w.x = bf16x2_pack(acc[mt][nt][0], acc[mt][nt][1]);
            w.y = bf16x2_pack(acc[mt][nt][2], acc[mt][nt][3]);
            *(uint2*)&Ptile[idx] = w;
        }
    }
}

// ------------- GEMM 1: M = proj(compact) @ compact(f)^T, fused max --------------
// A (proj) via cp.async (3-stage); B (compact f cols) via registers (2-stage).
__global__ void __launch_bounds__(256, 2) gemm1_kernel(const float* __restrict__ F)
{
    __shared__ __align__(16) uint32_t As[3][2048];
    __shared__ __align__(16) uint32_t Bs[2][2048];
    __shared__ float s_rmax[128];
    __shared__ float s_cmax[128];

    const int tid  = threadIdx.x;
    const int lane = tid & 31;
    const int wid  = tid >> 5;
    const int wm   = wid & 1;
    const int wn   = wid >> 1;
    const int b  = blockIdx.z;
    const int l0 = blockIdx.y * 128;
    const int n0 = blockIdx.x * 128;

    const int cnt_t = g_cnt_t[b];
    const int cnt_f = g_cnt_f[b];
    if (l0 >= cnt_t || n0 >= cnt_f) return;

    const int gr = tid >> 2;
    const int gc = (tid & 3) * 4;
    const int p0 = gc >> 1;
    const int physL = lane ^ (lane >> 3);
    const float NINF = __int_as_float(0xff800000);

    const int j0 = n0 + gr, j1 = n0 + gr + 64;
    const bool pr0 = (j0 < cnt_f), pr1 = (j1 < cnt_f);
    const int c0 = pr0 ? g_idx_f[b * LL + j0] : 0;
    const int c1 = pr1 ? g_idx_f[b * LL + j1] : 0;

    if (tid < 128) { s_rmax[tid] = NINF; s_cmax[tid] = NINF; }

    const uint32_t* Ptile = g_projb + ((size_t)b * 4 + blockIdx.y) * 16 * 2048 + tid * 8;
    const float* Fb0 = F + ((size_t)b * LL + c0) * DD + gc;
    const float* Fb1 = F + ((size_t)b * LL + c1) * DD + gc;

    uint32_t as_u32[3];
#pragma unroll
    for (int s = 0; s < 3; s++)
        as_u32[s] = (uint32_t)__cvta_generic_to_shared(&As[s][tid * 8]);

    float acc[4][4][4];
#pragma unroll
    for (int i = 0; i < 4; i++)
#pragma unroll
        for (int j = 0; j < 4; j++)
#pragma unroll
            for (int q = 0; q < 4; q++) acc[i][j][q] = 0.0f;

    // prologue
    CP_ASYNC16(as_u32[0],      Ptile);
    CP_ASYNC16(as_u32[0] + 16, Ptile + 4);
    CP_COMMIT();
    CP_ASYNC16(as_u32[1],      Ptile + 2048);
    CP_ASYNC16(as_u32[1] + 16, Ptile + 2048 + 4);
    CP_COMMIT();
    {
        float4 v;
        v = zmask(*(const float4*)(Fb0), pr0);      stB_nm(Bs[0], gr,      0, p0, v);
        v = zmask(*(const float4*)(Fb0 + 16), pr0); stB_nm(Bs[0], gr,      1, p0, v);
        v = zmask(*(const float4*)(Fb1), pr1);      stB_nm(Bs[0], gr + 64, 0, p0, v);
        v = zmask(*(const float4*)(Fb1 + 16), pr1); stB_nm(Bs[0], gr + 64, 1, p0, v);
    }
    CP_WAIT1();
    __syncthreads();

    for (int kt = 0; kt < 16; kt++) {
        const int buf2 = kt & 1;
        const int buf3 = kt % 3;
        const bool more = (kt + 1 < 16);

        float4 vb0, vb1, vb2, vb3;
        if (more) {
            const int K0 = (kt + 1) * 32;
            vb0 = zmask(*(const float4*)(Fb0 + K0), pr0);
            vb1 = zmask(*(const float4*)(Fb0 + K0 + 16), pr0);
            vb2 = zmask(*(const float4*)(Fb1 + K0), pr1);
            vb3 = zmask(*(const float4*)(Fb1 + K0 + 16), pr1);
        }
        if (kt + 2 < 16) {
            const int s3 = (kt + 2) % 3;
            CP_ASYNC16(as_u32[s3],      Ptile + (size_t)(kt + 2) * 2048);
            CP_ASYNC16(as_u32[s3] + 16, Ptile + (size_t)(kt + 2) * 2048 + 4);
            CP_COMMIT();
        }

        mma_block(As[buf3], Bs[buf2], 0, wm, wn, physL, acc);

        if (more) {
            stB_nm(Bs[buf2 ^ 1], gr,      0, p0, vb0);
            stB_nm(Bs[buf2 ^ 1], gr,      1, p0, vb1);
            stB_nm(Bs[buf2 ^ 1], gr + 64, 0, p0, vb2);
            stB_nm(Bs[buf2 ^ 1], gr + 64, 1, p0, vb3);
        }

        mma_block(As[buf3], Bs[buf2], 1, wm, wn, physL, acc);

        if (more) {
            if (kt + 2 < 16) { CP_WAIT1(); } else { CP_WAIT0(); }
            __syncthreads();
        }
    }

    // fused row/col max epilogue with index scatter
    __syncthreads();
    const int lx = lane & 3, ly = lane >> 2;
#pragma unroll
    for (int mt = 0; mt < 4; mt++) {
#pragma unroll
        for (int h = 0; h < 2; h++) {
            float v = NINF;
#pragma unroll
            for (int nt = 0; nt < 4; nt++)
                v = fmaxf(v, fmaxf(acc[mt][nt][2 * h], acc[mt][nt][2 * h + 1]));
            v = fmaxf(v, __shfl_xor_sync(0xffffffffu, v, 1));
            v = fmaxf(v, __shfl_xor_sync(0xffffffffu, v, 2));
            if (lx == 0) atomicMaxF(&s_rmax[wm * 64 + mt * 16 + ly + h * 8], v);
        }
    }
#pragma unroll
    for (int nt = 0; nt < 4; nt++) {
#pragma unroll
        for (int j = 0; j < 2; j++) {
            float v = NINF;
#pragma unroll
            for (int mt = 0; mt < 4; mt++)
                v = fmaxf(v, fmaxf(acc[mt][nt][j], acc[mt][nt][2 + j]));
            v = fmaxf(v, __shfl_xor_sync(0xffffffffu, v, 4));
            v = fmaxf(v, __shfl_xor_sync(0xffffffffu, v, 8));
            v = fmaxf(v, __shfl_xor_sync(0xffffffffu, v, 16));
            if (lane < 4) atomicMaxF(&s_cmax[wn * 32 + nt * 8 + 2 * lane + j], v);
        }
    }
    __syncthreads();
    if (tid < 128) {
        const int jr = l0 + tid;
        if (jr < cnt_t)
            atomicMaxF(&g_rowmax[b * LL + g_idx_t[b * LL + jr]], s_rmax[tid]);
        const int jc = n0 + tid;
        if (jc < cnt_f)
            atomicMaxF(&g_colmax[b * LL + g_idx_f[b * LL + jc]], s_cmax[tid]);
    }
}

// ----------------------------- softmax ----------------------------------------
__global__ void softmax_kernel() {
    const int idx = blockIdx.x;
    const bool isF = idx >= Bb;
    const int b = isF ? idx - Bb : idx;
    const float* mx = isF ? (g_colmax + b * LL) : (g_rowmax + b * LL);
    const float* mk = isF ? (g_mf + b * LL) : (g_mt + b * LL);
    float* out = isF ? (g_alpha_f + b * LL) : (g_alpha_t + b * LL);
    // opposite-axis count: if any opposite lane is masked, reference max includes tanh(0)=0
    const int cnt_other = isF ? g_cnt_t[b] : g_cnt_f[b];

    const int tid = threadIdx.x;
    int i0 = tid, i1 = tid + 256;
    float m0v = mk[i0], m1v = mk[i1];
    float x0 = mx[i0], x1 = mx[i1];
    if (cnt_other < 512) { x0 = fmaxf(x0, 0.0f); x1 = fmaxf(x1, 0.0f); }
    float v0 = tanhf(x0) + (m0v - 1.0f) * 1000000.0f;
    float v1 = tanhf(x1) + (m1v - 1.0f) * 1000000.0f;

    __shared__ float red[256];
    red[tid] = fmaxf(v0, v1);
    __syncthreads();
    for (int s = 128; s > 0; s >>= 1) {
        if (tid < s) red[tid] = fmaxf(red[tid], red[tid + s]);
        __syncthreads();
    }
    float vm = red[0];
    __syncthreads();

    float e0 = expf(v0 - vm);
    float e1 = expf(v1 - vm);
    red[tid] = e0 + e1;
    __syncthreads();
    for (int s = 128; s > 0; s >>= 1) {
        if (tid < s) red[tid] += red[tid + s];
        __syncthreads();
    }
    float inv = 1.0f / red[0];
    out[i0] = e0 * inv * m0v;
    out[i1] = e1 * inv * m1v;
}

// ----------------------------- combine (compact) --------------------------------
// grid (4, Bb), block 1024: 8 compact-chunks of 64, smem reduce.
__global__ void combine_kernel(const float* __restrict__ T,
                               const float* __restrict__ F,
                               float* __restrict__ out)
{
    __shared__ float red[1024];
    const int b = blockIdx.y;
    const int dl = threadIdx.x & 127;
    const int chunk = threadIdx.x >> 7;           // 0..7
    const int d = blockIdx.x * 128 + dl;
    const int* it  = g_idx_t + b * LL;
    const int* ifx = g_idx_f + b * LL;
    const int ct = g_cnt_t[b], cf = g_cnt_f[b];
    const float* at = g_alpha_t + b * LL;
    const float* af = g_alpha_f + b * LL;
    const float* tp = T + (size_t)b * LL * DD + d;
    const float* fp = F + (size_t)b * LL * DD + d;
    const int jb = chunk * 64;

    float a0 = 0.f, a1 = 0.f, a2 = 0.f, a3 = 0.f;
    {
        const int je = min(jb + 64, ct);
        int j = jb;
        for (; j + 4 <= je; j += 4) {
            int l0 = it[j], l1 = it[j + 1], l2 = it[j + 2], l3 = it[j + 3];
            a0 = fmaf(at[l0], tp[(size_t)l0 * DD], a0);
            a1 = fmaf(at[l1], tp[(size_t)l1 * DD], a1);
            a2 = fmaf(at[l2], tp[(size_t)l2 * DD], a2);
            a3 = fmaf(at[l3], tp[(size_t)l3 * DD], a3);
        }
        for (; j < je; j++) {
            int l = it[j];
            a0 = fmaf(at[l], tp[(size_t)l * DD], a0);
        }
    }
    {
        const int je = min(jb + 64, cf);
        int j = jb;
        for (; j + 4 <= je; j += 4) {
            int l0 = ifx[j], l1 = ifx[j + 1], l2 = ifx[j + 2], l3 = ifx[j + 3];
            a0 = fmaf(af[l0], fp[(size_t)l0 * DD], a0);
            a1 = fmaf(af[l1], fp[(size_t)l1 * DD], a1);
            a2 = fmaf(af[l2], fp[(size_t)l2 * DD], a2);
            a3 = fmaf(af[l3], fp[(size_t)l3 * DD], a3);
        }
        for (; j < je; j++) {
            int l = ifx[j];
            a0 = fmaf(af[l], fp[(size_t)l * DD], a0);
        }
    }
    red[threadIdx.x] = (a0 + a1) + (a2 + a3);
    __syncthreads();
    if (chunk == 0) {
        float s = 0.f;
#pragma unroll
        for (int i = 0; i < 8; i++) s += red[dl + 128 * i];
        out[b * DD + d] = s;
    }
}

// ----------------------------- launch -------------------------------------------
extern "C" void kernel_launch(void* const* d_in, const int* in_sizes, int n_in,
                              void* d_out, int out_size)
{
    const float* t  = (const float*)d_in[0];
    const float* f  = (const float*)d_in[1];
    const void*  mt = d_in[2];
    const void*  mf = d_in[3];
    const float* w  = (const float*)d_in[4];
    float* out = (float*)d_out;

    detect_kernel<<<1, 32>>>((const unsigned int*)mt);
    compact_kernel<<<2 * Bb, 512>>>(mt, mf);
    pack_w<<<256, 512>>>(w);
    gemm0_kernel<<<dim3(4, 4, Bb), 256>>>(t);
    gemm1_kernel<<<dim3(4, 4, Bb), 256>>>(f);
    softmax_kernel<<<2 * Bb, 256>>>();
    combine_kernel<<<dim3(4, Bb), 1024>>>(t, f, out);
}